// round 2
// baseline (speedup 1.0000x reference)
#include <cuda_runtime.h>

// ---------------------------------------------------------------------------
// CausalSelfAttention: B=2, T=2048, C=1024, H=16, D=64, fp32
//   q/k/v = x @ W{q,k,v}.T + b   -> [B,H,T,D]
//   y = causal softmax(q k^T / 8) v  -> [B,T,C]
//   out = y @ Wp.T + bp
// Round 1: fp32 SIMT baseline. Tiled NT-GEMM + fused flash attention.
// ---------------------------------------------------------------------------

#define Bc 2
#define Tc 2048
#define Cc 1024
#define Hc 16
#define Dc 64

__device__ float g_q[Bc * Hc * Tc * Dc];
__device__ float g_k[Bc * Hc * Tc * Dc];
__device__ float g_v[Bc * Hc * Tc * Dc];
__device__ float g_y[Bc * Tc * Cc];

// ---------------------------------------------------------------------------
// NT GEMM: C[m,n] = sum_k A[m,k] * B[n,k] + bias[n]
// A: [M,K] row-major, B: [N,K] row-major. M=4096, N=1024, K=1024 (all /128, /16).
// MODE 0: scatter into split-head layout [B,H,T,D]; MODE 1: plain [M,N].
// ---------------------------------------------------------------------------
#define GBM 128
#define GBN 128
#define GBK 16

template <int MODE>
__global__ void __launch_bounds__(256)
gemm_nt(const float* __restrict__ A, const float* __restrict__ B,
        const float* __restrict__ bias, float* __restrict__ C,
        int M, int N, int K)
{
    __shared__ __align__(16) float As[GBK][GBM];
    __shared__ __align__(16) float Bs[GBK][GBN];

    const int tid = threadIdx.x;
    const int m0 = blockIdx.y * GBM;
    const int n0 = blockIdx.x * GBN;
    const int row = (tid >> 4) << 3;  // (tid/16)*8
    const int col = (tid & 15) << 3;  // (tid%16)*8

    float acc[8][8];
#pragma unroll
    for (int i = 0; i < 8; i++)
#pragma unroll
        for (int j = 0; j < 8; j++) acc[i][j] = 0.f;

    for (int k0 = 0; k0 < K; k0 += GBK) {
#pragma unroll
        for (int it = 0; it < 2; it++) {
            int e  = tid + it * 256;   // 0..511
            int r  = e >> 2;
            int c4 = (e & 3) << 2;
            float4 va = *reinterpret_cast<const float4*>(&A[(size_t)(m0 + r) * K + k0 + c4]);
            As[c4 + 0][r] = va.x; As[c4 + 1][r] = va.y;
            As[c4 + 2][r] = va.z; As[c4 + 3][r] = va.w;
            float4 vb = *reinterpret_cast<const float4*>(&B[(size_t)(n0 + r) * K + k0 + c4]);
            Bs[c4 + 0][r] = vb.x; Bs[c4 + 1][r] = vb.y;
            Bs[c4 + 2][r] = vb.z; Bs[c4 + 3][r] = vb.w;
        }
        __syncthreads();

#pragma unroll
        for (int k = 0; k < GBK; k++) {
            float a[8], b[8];
            *reinterpret_cast<float4*>(&a[0]) = *reinterpret_cast<const float4*>(&As[k][row]);
            *reinterpret_cast<float4*>(&a[4]) = *reinterpret_cast<const float4*>(&As[k][row + 4]);
            *reinterpret_cast<float4*>(&b[0]) = *reinterpret_cast<const float4*>(&Bs[k][col]);
            *reinterpret_cast<float4*>(&b[4]) = *reinterpret_cast<const float4*>(&Bs[k][col + 4]);
#pragma unroll
            for (int i = 0; i < 8; i++)
#pragma unroll
                for (int j = 0; j < 8; j++) acc[i][j] += a[i] * b[j];
        }
        __syncthreads();
    }

#pragma unroll
    for (int i = 0; i < 8; i++) {
        int m = m0 + row + i;
#pragma unroll
        for (int j = 0; j < 8; j++) {
            int n = n0 + col + j;
            float val = acc[i][j] + bias[n];
            if (MODE == 0) {
                // [B,H,T,D]: b=m/T, t=m%T, h=n/D, d=n%D
                int bb = m >> 11;          // /2048
                int tt = m & 2047;
                int hh = n >> 6;           // /64
                int dd = n & 63;
                C[((size_t)((bb * Hc + hh) * Tc + tt) << 6) + dd] = val;
            } else {
                C[(size_t)m * N + n] = val;
            }
        }
    }
}

// ---------------------------------------------------------------------------
// Flash attention, fp32, causal. Per block: 64 queries of one (b,h).
// 256 threads: thread = (row r = tid/4, group g = tid%4).
// Thread owns columns/dims c = g + 4*i, i in 0..15 (interleaved).
// Smem: Q,K,V tiles 64x64 fp32 each, XOR-swizzled at float4 granularity
// (16 float4 cols, col4' = col4 ^ (row & 15)) -> conflict-free, exactly 48KB.
// Scores kept in registers, exchanged via shfl within the 4-lane row group.
// ---------------------------------------------------------------------------
__device__ __forceinline__ int sw4(int row, int c4) { return row * 16 + (c4 ^ (row & 15)); }

__global__ void __launch_bounds__(256)
flash_attn(const float* __restrict__ Q, const float* __restrict__ K,
           const float* __restrict__ V, float* __restrict__ Y)
{
    __shared__ __align__(16) float Qs[64 * 64];
    __shared__ __align__(16) float Ks[64 * 64];
    __shared__ __align__(16) float Vs[64 * 64];

    const int bh  = blockIdx.y;        // 0..B*H-1
    const int b   = bh >> 4;
    const int h   = bh & 15;
    const int m0  = blockIdx.x << 6;
    const int tid = threadIdx.x;
    const int r   = tid >> 2;
    const int g   = tid & 3;
    const size_t base = (size_t)bh * Tc * Dc;

    // Load Q tile (swizzled)
#pragma unroll
    for (int it = 0; it < 4; it++) {
        int e  = tid + it * 256;
        int rr = e >> 4;
        int c4 = e & 15;
        reinterpret_cast<float4*>(Qs)[sw4(rr, c4)] =
            *reinterpret_cast<const float4*>(&Q[base + (size_t)(m0 + rr) * Dc + (c4 << 2)]);
    }

    float acc[16];
#pragma unroll
    for (int i = 0; i < 16; i++) acc[i] = 0.f;
    float m_i = -1e30f, l_i = 0.f;
    const float scale = 0.125f;   // 1/sqrt(64)

    const int nkv = blockIdx.x + 1;   // causal: only kv tiles <= q tile
    for (int j = 0; j < nkv; j++) {
        const int n0 = j << 6;
        __syncthreads();
#pragma unroll
        for (int it = 0; it < 4; it++) {
            int e  = tid + it * 256;
            int rr = e >> 4;
            int c4 = e & 15;
            reinterpret_cast<float4*>(Ks)[sw4(rr, c4)] =
                *reinterpret_cast<const float4*>(&K[base + (size_t)(n0 + rr) * Dc + (c4 << 2)]);
            reinterpret_cast<float4*>(Vs)[sw4(rr, c4)] =
                *reinterpret_cast<const float4*>(&V[base + (size_t)(n0 + rr) * Dc + (c4 << 2)]);
        }
        __syncthreads();

        // ---- scores: s[i] = Q[r,:] . K[g+4i,:] ----
        float s[16];
#pragma unroll
        for (int i = 0; i < 16; i++) s[i] = 0.f;
#pragma unroll
        for (int c4 = 0; c4 < 16; c4++) {
            float4 q4 = reinterpret_cast<const float4*>(Qs)[sw4(r, c4)];
#pragma unroll
            for (int i = 0; i < 16; i++) {
                int c = g + (i << 2);
                float4 k4 = reinterpret_cast<const float4*>(Ks)[sw4(c, c4)];
                s[i] += q4.x * k4.x + q4.y * k4.y + q4.z * k4.z + q4.w * k4.w;
            }
        }

        // ---- scale + causal mask + online softmax ----
        const bool diag = (j == nkv - 1);
        float mloc = -1e30f;
#pragma unroll
        for (int i = 0; i < 16; i++) {
            s[i] *= scale;
            if (diag && (n0 + g + (i << 2)) > (m0 + r)) s[i] = -1e30f;
            mloc = fmaxf(mloc, s[i]);
        }
        mloc = fmaxf(mloc, __shfl_xor_sync(0xffffffffu, mloc, 1));
        mloc = fmaxf(mloc, __shfl_xor_sync(0xffffffffu, mloc, 2));
        float m_new = fmaxf(m_i, mloc);
        float alpha = __expf(m_i - m_new);
        float lloc = 0.f;
#pragma unroll
        for (int i = 0; i < 16; i++) {
            s[i] = __expf(s[i] - m_new);
            lloc += s[i];
        }
        lloc += __shfl_xor_sync(0xffffffffu, lloc, 1);
        lloc += __shfl_xor_sync(0xffffffffu, lloc, 2);
        l_i = l_i * alpha + lloc;
        m_i = m_new;
#pragma unroll
        for (int i = 0; i < 16; i++) acc[i] *= alpha;

        // ---- PV: acc[i] += sum_c P[r,c] * V[c, g+4i] ----
        // P[r,c] lives in lane (c&3) of this row group at register index c>>2.
#pragma unroll
        for (int c = 0; c < 64; c++) {
            float p = __shfl_sync(0xffffffffu, s[c >> 2], c & 3, 4);
            const float* vrow = &Vs[c << 6];       // row c base (64 floats)
            int xr = c & 15;
#pragma unroll
            for (int i = 0; i < 16; i++) {
                // element (c, d) with d = g + 4i -> float4 idx (i ^ xr), lane g
                float vv = vrow[(((i ^ xr) << 2)) + g];
                acc[i] += p * vv;
            }
        }
    }

    const float inv = 1.0f / l_i;
    const size_t orow = (size_t)(b * Tc + m0 + r) * Cc + (h << 6);
#pragma unroll
    for (int i = 0; i < 16; i++)
        Y[orow + g + (i << 2)] = acc[i] * inv;
}

// ---------------------------------------------------------------------------
extern "C" void kernel_launch(void* const* d_in, const int* in_sizes, int n_in,
                              void* d_out, int out_size)
{
    const float* x  = (const float*)d_in[0];
    const float* Wk = (const float*)d_in[1];
    const float* bk = (const float*)d_in[2];
    const float* Wq = (const float*)d_in[3];
    const float* bq = (const float*)d_in[4];
    const float* Wv = (const float*)d_in[5];
    const float* bv = (const float*)d_in[6];
    const float* Wp = (const float*)d_in[7];
    const float* bp = (const float*)d_in[8];
    float* out = (float*)d_out;

    float *pq, *pk, *pv, *py;
    cudaGetSymbolAddress((void**)&pq, g_q);
    cudaGetSymbolAddress((void**)&pk, g_k);
    cudaGetSymbolAddress((void**)&pv, g_v);
    cudaGetSymbolAddress((void**)&py, g_y);

    const int M = Bc * Tc;   // 4096
    const int N = Cc;        // 1024
    const int K = Cc;        // 1024

    dim3 gg(N / GBN, M / GBM);   // (8, 32)
    gemm_nt<0><<<gg, 256>>>(x, Wq, bq, pq, M, N, K);
    gemm_nt<0><<<gg, 256>>>(x, Wk, bk, pk, M, N, K);
    gemm_nt<0><<<gg, 256>>>(x, Wv, bv, pv, M, N, K);

    dim3 fg(Tc / 64, Bc * Hc);   // (32, 32)
    flash_attn<<<fg, 256>>>(pq, pk, pv, py);

    gemm_nt<1><<<gg, 256>>>(py, Wp, bp, out, M, N, K);
}

// round 3
// speedup vs baseline: 1.0008x; 1.0008x over previous
#include <cuda_runtime.h>

// ---------------------------------------------------------------------------
// CausalSelfAttention: B=2, T=2048, C=1024, H=16, D=64, fp32
//   q/k/v = x @ W{q,k,v}.T + b   -> [B,H,T,D]
//   y = causal softmax(q k^T / 8) v  -> [B,T,C]
//   out = y @ Wp.T + bp
// Round 1: fp32 SIMT baseline. Tiled NT-GEMM + fused flash attention.
// ---------------------------------------------------------------------------

#define Bc 2
#define Tc 2048
#define Cc 1024
#define Hc 16
#define Dc 64

__device__ float g_q[Bc * Hc * Tc * Dc];
__device__ float g_k[Bc * Hc * Tc * Dc];
__device__ float g_v[Bc * Hc * Tc * Dc];
__device__ float g_y[Bc * Tc * Cc];

// ---------------------------------------------------------------------------
// NT GEMM: C[m,n] = sum_k A[m,k] * B[n,k] + bias[n]
// A: [M,K] row-major, B: [N,K] row-major. M=4096, N=1024, K=1024 (all /128, /16).
// MODE 0: scatter into split-head layout [B,H,T,D]; MODE 1: plain [M,N].
// ---------------------------------------------------------------------------
#define GBM 128
#define GBN 128
#define GBK 16

template <int MODE>
__global__ void __launch_bounds__(256)
gemm_nt(const float* __restrict__ A, const float* __restrict__ B,
        const float* __restrict__ bias, float* __restrict__ C,
        int M, int N, int K)
{
    __shared__ __align__(16) float As[GBK][GBM];
    __shared__ __align__(16) float Bs[GBK][GBN];

    const int tid = threadIdx.x;
    const int m0 = blockIdx.y * GBM;
    const int n0 = blockIdx.x * GBN;
    const int row = (tid >> 4) << 3;  // (tid/16)*8
    const int col = (tid & 15) << 3;  // (tid%16)*8

    float acc[8][8];
#pragma unroll
    for (int i = 0; i < 8; i++)
#pragma unroll
        for (int j = 0; j < 8; j++) acc[i][j] = 0.f;

    for (int k0 = 0; k0 < K; k0 += GBK) {
#pragma unroll
        for (int it = 0; it < 2; it++) {
            int e  = tid + it * 256;   // 0..511
            int r  = e >> 2;
            int c4 = (e & 3) << 2;
            float4 va = *reinterpret_cast<const float4*>(&A[(size_t)(m0 + r) * K + k0 + c4]);
            As[c4 + 0][r] = va.x; As[c4 + 1][r] = va.y;
            As[c4 + 2][r] = va.z; As[c4 + 3][r] = va.w;
            float4 vb = *reinterpret_cast<const float4*>(&B[(size_t)(n0 + r) * K + k0 + c4]);
            Bs[c4 + 0][r] = vb.x; Bs[c4 + 1][r] = vb.y;
            Bs[c4 + 2][r] = vb.z; Bs[c4 + 3][r] = vb.w;
        }
        __syncthreads();

#pragma unroll
        for (int k = 0; k < GBK; k++) {
            float a[8], b[8];
            *reinterpret_cast<float4*>(&a[0]) = *reinterpret_cast<const float4*>(&As[k][row]);
            *reinterpret_cast<float4*>(&a[4]) = *reinterpret_cast<const float4*>(&As[k][row + 4]);
            *reinterpret_cast<float4*>(&b[0]) = *reinterpret_cast<const float4*>(&Bs[k][col]);
            *reinterpret_cast<float4*>(&b[4]) = *reinterpret_cast<const float4*>(&Bs[k][col + 4]);
#pragma unroll
            for (int i = 0; i < 8; i++)
#pragma unroll
                for (int j = 0; j < 8; j++) acc[i][j] += a[i] * b[j];
        }
        __syncthreads();
    }

#pragma unroll
    for (int i = 0; i < 8; i++) {
        int m = m0 + row + i;
#pragma unroll
        for (int j = 0; j < 8; j++) {
            int n = n0 + col + j;
            float val = acc[i][j] + bias[n];
            if (MODE == 0) {
                // [B,H,T,D]: b=m/T, t=m%T, h=n/D, d=n%D
                int bb = m >> 11;          // /2048
                int tt = m & 2047;
                int hh = n >> 6;           // /64
                int dd = n & 63;
                C[((size_t)((bb * Hc + hh) * Tc + tt) << 6) + dd] = val;
            } else {
                C[(size_t)m * N + n] = val;
            }
        }
    }
}

// ---------------------------------------------------------------------------
// Flash attention, fp32, causal. Per block: 64 queries of one (b,h).
// 256 threads: thread = (row r = tid/4, group g = tid%4).
// Thread owns columns/dims c = g + 4*i, i in 0..15 (interleaved).
// Smem: Q,K,V tiles 64x64 fp32 each, XOR-swizzled at float4 granularity
// (16 float4 cols, col4' = col4 ^ (row & 15)) -> conflict-free, exactly 48KB.
// Scores kept in registers, exchanged via shfl within the 4-lane row group.
// ---------------------------------------------------------------------------
__device__ __forceinline__ int sw4(int row, int c4) { return row * 16 + (c4 ^ (row & 15)); }

__global__ void __launch_bounds__(256)
flash_attn(const float* __restrict__ Q, const float* __restrict__ K,
           const float* __restrict__ V, float* __restrict__ Y)
{
    __shared__ __align__(16) float Qs[64 * 64];
    __shared__ __align__(16) float Ks[64 * 64];
    __shared__ __align__(16) float Vs[64 * 64];

    const int bh  = blockIdx.y;        // 0..B*H-1
    const int b   = bh >> 4;
    const int h   = bh & 15;
    const int m0  = blockIdx.x << 6;
    const int tid = threadIdx.x;
    const int r   = tid >> 2;
    const int g   = tid & 3;
    const size_t base = (size_t)bh * Tc * Dc;

    // Load Q tile (swizzled)
#pragma unroll
    for (int it = 0; it < 4; it++) {
        int e  = tid + it * 256;
        int rr = e >> 4;
        int c4 = e & 15;
        reinterpret_cast<float4*>(Qs)[sw4(rr, c4)] =
            *reinterpret_cast<const float4*>(&Q[base + (size_t)(m0 + rr) * Dc + (c4 << 2)]);
    }

    float acc[16];
#pragma unroll
    for (int i = 0; i < 16; i++) acc[i] = 0.f;
    float m_i = -1e30f, l_i = 0.f;
    const float scale = 0.125f;   // 1/sqrt(64)

    const int nkv = blockIdx.x + 1;   // causal: only kv tiles <= q tile
    for (int j = 0; j < nkv; j++) {
        const int n0 = j << 6;
        __syncthreads();
#pragma unroll
        for (int it = 0; it < 4; it++) {
            int e  = tid + it * 256;
            int rr = e >> 4;
            int c4 = e & 15;
            reinterpret_cast<float4*>(Ks)[sw4(rr, c4)] =
                *reinterpret_cast<const float4*>(&K[base + (size_t)(n0 + rr) * Dc + (c4 << 2)]);
            reinterpret_cast<float4*>(Vs)[sw4(rr, c4)] =
                *reinterpret_cast<const float4*>(&V[base + (size_t)(n0 + rr) * Dc + (c4 << 2)]);
        }
        __syncthreads();

        // ---- scores: s[i] = Q[r,:] . K[g+4i,:] ----
        float s[16];
#pragma unroll
        for (int i = 0; i < 16; i++) s[i] = 0.f;
#pragma unroll
        for (int c4 = 0; c4 < 16; c4++) {
            float4 q4 = reinterpret_cast<const float4*>(Qs)[sw4(r, c4)];
#pragma unroll
            for (int i = 0; i < 16; i++) {
                int c = g + (i << 2);
                float4 k4 = reinterpret_cast<const float4*>(Ks)[sw4(c, c4)];
                s[i] += q4.x * k4.x + q4.y * k4.y + q4.z * k4.z + q4.w * k4.w;
            }
        }

        // ---- scale + causal mask + online softmax ----
        const bool diag = (j == nkv - 1);
        float mloc = -1e30f;
#pragma unroll
        for (int i = 0; i < 16; i++) {
            s[i] *= scale;
            if (diag && (n0 + g + (i << 2)) > (m0 + r)) s[i] = -1e30f;
            mloc = fmaxf(mloc, s[i]);
        }
        mloc = fmaxf(mloc, __shfl_xor_sync(0xffffffffu, mloc, 1));
        mloc = fmaxf(mloc, __shfl_xor_sync(0xffffffffu, mloc, 2));
        float m_new = fmaxf(m_i, mloc);
        float alpha = __expf(m_i - m_new);
        float lloc = 0.f;
#pragma unroll
        for (int i = 0; i < 16; i++) {
            s[i] = __expf(s[i] - m_new);
            lloc += s[i];
        }
        lloc += __shfl_xor_sync(0xffffffffu, lloc, 1);
        lloc += __shfl_xor_sync(0xffffffffu, lloc, 2);
        l_i = l_i * alpha + lloc;
        m_i = m_new;
#pragma unroll
        for (int i = 0; i < 16; i++) acc[i] *= alpha;

        // ---- PV: acc[i] += sum_c P[r,c] * V[c, g+4i] ----
        // P[r,c] lives in lane (c&3) of this row group at register index c>>2.
#pragma unroll
        for (int c = 0; c < 64; c++) {
            float p = __shfl_sync(0xffffffffu, s[c >> 2], c & 3, 4);
            const float* vrow = &Vs[c << 6];       // row c base (64 floats)
            int xr = c & 15;
#pragma unroll
            for (int i = 0; i < 16; i++) {
                // element (c, d) with d = g + 4i -> float4 idx (i ^ xr), lane g
                float vv = vrow[(((i ^ xr) << 2)) + g];
                acc[i] += p * vv;
            }
        }
    }

    const float inv = 1.0f / l_i;
    const size_t orow = (size_t)(b * Tc + m0 + r) * Cc + (h << 6);
#pragma unroll
    for (int i = 0; i < 16; i++)
        Y[orow + g + (i << 2)] = acc[i] * inv;
}

// ---------------------------------------------------------------------------
extern "C" void kernel_launch(void* const* d_in, const int* in_sizes, int n_in,
                              void* d_out, int out_size)
{
    const float* x  = (const float*)d_in[0];
    const float* Wk = (const float*)d_in[1];
    const float* bk = (const float*)d_in[2];
    const float* Wq = (const float*)d_in[3];
    const float* bq = (const float*)d_in[4];
    const float* Wv = (const float*)d_in[5];
    const float* bv = (const float*)d_in[6];
    const float* Wp = (const float*)d_in[7];
    const float* bp = (const float*)d_in[8];
    float* out = (float*)d_out;

    float *pq, *pk, *pv, *py;
    cudaGetSymbolAddress((void**)&pq, g_q);
    cudaGetSymbolAddress((void**)&pk, g_k);
    cudaGetSymbolAddress((void**)&pv, g_v);
    cudaGetSymbolAddress((void**)&py, g_y);

    const int M = Bc * Tc;   // 4096
    const int N = Cc;        // 1024
    const int K = Cc;        // 1024

    dim3 gg(N / GBN, M / GBM);   // (8, 32)
    gemm_nt<0><<<gg, 256>>>(x, Wq, bq, pq, M, N, K);
    gemm_nt<0><<<gg, 256>>>(x, Wk, bk, pk, M, N, K);
    gemm_nt<0><<<gg, 256>>>(x, Wv, bv, pv, M, N, K);

    dim3 fg(Tc / 64, Bc * Hc);   // (32, 32)
    flash_attn<<<fg, 256>>>(pq, pk, pv, py);

    gemm_nt<1><<<gg, 256>>>(py, Wp, bp, out, M, N, K);
}